// round 5
// baseline (speedup 1.0000x reference)
#include <cuda_runtime.h>
#include <math.h>
#include <stdint.h>

#define BB 4
#define SS 2048
#define DM 2048
#define HH 16
#define DHD 128
#define MAXL 1024
#define SM_SCALE 0.08838834764831845f  // 1/sqrt(128)

// ---------------- scratch (device globals; no allocation allowed) ----------
__device__ float g_Q[(size_t)BB * MAXL * DM];   // 33.5 MB
__device__ float g_K[(size_t)BB * SS * DM];     // 67 MB
__device__ float g_V[(size_t)BB * SS * DM];     // 67 MB
__device__ float g_CTX[(size_t)BB * MAXL * DM]; // 33.5 MB
__device__ int   g_order[BB * MAXL];
__device__ int   g_posq[BB * MAXL];
__device__ int   g_nb[BB];
__device__ float g_invfreq[64];
__device__ int   g_bool_kind;  // 0 = uint8, 1 = int32, 2 = float32

// ---------------- inv_freq init (match jax 10000**(j/64) in double) --------
__global__ void init_invfreq_kernel() {
    int j = threadIdx.x;
    if (j < 64) g_invfreq[j] = (float)(1.0 / pow(10000.0, (double)j / 64.0));
}

// ---------------- detect storage dtype of the bool skip_mask ---------------
__global__ void detect_bool_kernel(const unsigned int* __restrict__ w) {
    __shared__ int c01, c0f;
    if (threadIdx.x == 0) { c01 = 0; c0f = 0; }
    __syncthreads();
    int a = 0, f = 0;
    for (int i = threadIdx.x; i < 2048; i += blockDim.x) {
        unsigned int v = w[i];
        if (v == 0u || v == 1u) a++;
        if (v == 0u || v == 0x3F800000u) f++;
    }
    atomicAdd(&c01, a);
    atomicAdd(&c0f, f);
    __syncthreads();
    if (threadIdx.x == 0)
        g_bool_kind = (c01 == 2048) ? 1 : ((c0f == 2048) ? 2 : 0);
}

__device__ __forceinline__ int read_bool(const void* p, size_t i, int kind) {
    if (kind == 1) return ((const int*)p)[i] != 0;
    if (kind == 2) return ((const float*)p)[i] != 0.0f;
    return ((const unsigned char*)p)[i] != 0;
}

// ---------------- trim: stable True-first order + lengths + pos_trim -------
__global__ void trim_kernel(const void* __restrict__ skip,
                            const int* __restrict__ pos_full) {
    int b = blockIdx.x;
    int t = threadIdx.x;  // 1024 threads
    int kind = g_bool_kind;
    __shared__ int bufA[2048], bufB[2048];
    int m0 = read_bool(skip, (size_t)b * SS + t, kind);
    int m1 = read_bool(skip, (size_t)b * SS + t + 1024, kind);
    bufA[t] = m0;
    bufA[t + 1024] = m1;
    __syncthreads();
    int* srcb = bufA;
    int* dstb = bufB;
    for (int off = 1; off < 2048; off <<= 1) {
        int i0 = t, i1 = t + 1024;
        int v0 = srcb[i0] + (i0 >= off ? srcb[i0 - off] : 0);
        int v1 = srcb[i1] + (i1 >= off ? srcb[i1 - off] : 0);
        dstb[i0] = v0;
        dstb[i1] = v1;
        __syncthreads();
        int* tp = srcb; srcb = dstb; dstb = tp;
    }
    int total = srcb[2047];
    {
        int inc0 = srcb[t];
        int r0 = m0 ? (inc0 - 1) : (total + (t - inc0));
        if (r0 < MAXL) g_order[b * MAXL + r0] = t;
        int idx = t + 1024;
        int inc1 = srcb[idx];
        int r1 = m1 ? (inc1 - 1) : (total + (idx - inc1));
        if (r1 < MAXL) g_order[b * MAXL + r1] = idx;
    }
    __syncthreads();
    if (t < MAXL) {
        int s = g_order[b * MAXL + t];
        g_posq[b * MAXL + t] = (t < total) ? pos_full[b * SS + s] : 0;
    }
    if (t == 0) g_nb[b] = total;
}

// ---------------- SGEMM 128x128x16, double-buffered + reg prefetch ---------
__global__ void __launch_bounds__(256, 2) sgemm_db(const float* __restrict__ A,
                                                   const float* __restrict__ Bm,
                                                   float* __restrict__ C,
                                                   int M, int N, int K) {
    __shared__ float As[2][16][128];
    __shared__ float Bs[2][16][128];
    int tid = threadIdx.x;
    int tx = tid & 15, ty = tid >> 4;
    int row0 = blockIdx.y * 128, col0 = blockIdx.x * 128;

    // A staging map (coalesced: 4 lanes per row, 64B each): float4 idx tid, tid+256
    int ar = tid >> 2, ac = (tid & 3) << 2;       // ar in 0..63 for first, +64 second
    // B staging map: float4 idx tid (rows 0..7), tid+256 (rows 8..15)
    int br = tid >> 5, bc = (tid & 31) << 2;

    const float* Ap0 = A + (size_t)(row0 + ar) * K + ac;
    const float* Ap1 = A + (size_t)(row0 + ar + 64) * K + ac;
    const float* Bp0 = Bm + (size_t)br * N + col0 + bc;
    const float* Bp1 = Bm + (size_t)(br + 8) * N + col0 + bc;

    float acc[8][8];
#pragma unroll
    for (int i = 0; i < 8; i++)
#pragma unroll
        for (int j = 0; j < 8; j++) acc[i][j] = 0.f;

    const int NC = K >> 4;

    // ---- prologue: chunk 0 -> smem buf0, chunk 1 -> regs ----
    float4 pa0 = *(const float4*)Ap0;
    float4 pa1 = *(const float4*)Ap1;
    float4 pb0 = *(const float4*)Bp0;
    float4 pb1 = *(const float4*)Bp1;
    As[0][ac + 0][ar] = pa0.x; As[0][ac + 1][ar] = pa0.y;
    As[0][ac + 2][ar] = pa0.z; As[0][ac + 3][ar] = pa0.w;
    As[0][ac + 0][ar + 64] = pa1.x; As[0][ac + 1][ar + 64] = pa1.y;
    As[0][ac + 2][ar + 64] = pa1.z; As[0][ac + 3][ar + 64] = pa1.w;
    *(float4*)&Bs[0][br][bc] = pb0;
    *(float4*)&Bs[0][br + 8][bc] = pb1;
    pa0 = *(const float4*)(Ap0 + 16);
    pa1 = *(const float4*)(Ap1 + 16);
    pb0 = *(const float4*)(Bp0 + (size_t)16 * N);
    pb1 = *(const float4*)(Bp1 + (size_t)16 * N);
    __syncthreads();

    for (int c = 0; c < NC; ++c) {
        int buf = c & 1;
#pragma unroll
        for (int kk = 0; kk < 16; kk++) {
            float a[8], bb[8];
            *(float4*)&a[0] = *(float4*)&As[buf][kk][ty * 8];
            *(float4*)&a[4] = *(float4*)&As[buf][kk][ty * 8 + 4];
            *(float4*)&bb[0] = *(float4*)&Bs[buf][kk][tx * 8];
            *(float4*)&bb[4] = *(float4*)&Bs[buf][kk][tx * 8 + 4];
#pragma unroll
            for (int i = 0; i < 8; i++)
#pragma unroll
                for (int j = 0; j < 8; j++)
                    acc[i][j] = fmaf(a[i], bb[j], acc[i][j]);
        }
        if (c + 1 < NC) {
            int nb = buf ^ 1;
            // store prefetched chunk c+1 (buf^1 was last read in chunk c-1;
            // the barrier at the end of iteration c-1 protects it)
            As[nb][ac + 0][ar] = pa0.x; As[nb][ac + 1][ar] = pa0.y;
            As[nb][ac + 2][ar] = pa0.z; As[nb][ac + 3][ar] = pa0.w;
            As[nb][ac + 0][ar + 64] = pa1.x; As[nb][ac + 1][ar + 64] = pa1.y;
            As[nb][ac + 2][ar + 64] = pa1.z; As[nb][ac + 3][ar + 64] = pa1.w;
            *(float4*)&Bs[nb][br][bc] = pb0;
            *(float4*)&Bs[nb][br + 8][bc] = pb1;
            if (c + 2 < NC) {
                int ko = (c + 2) << 4;
                pa0 = *(const float4*)(Ap0 + ko);
                pa1 = *(const float4*)(Ap1 + ko);
                pb0 = *(const float4*)(Bp0 + (size_t)ko * N);
                pb1 = *(const float4*)(Bp1 + (size_t)ko * N);
            }
        }
        __syncthreads();
    }

#pragma unroll
    for (int i = 0; i < 8; i++) {
#pragma unroll
        for (int j4 = 0; j4 < 8; j4 += 4) {
            float4 v = make_float4(acc[i][j4], acc[i][j4 + 1], acc[i][j4 + 2], acc[i][j4 + 3]);
            *(float4*)&C[(size_t)(row0 + ty * 8 + i) * N + col0 + tx * 8 + j4] = v;
        }
    }
}

// ---------------- RoPE (in place on flat [rows, 2048]) ---------------------
__global__ void rope_kernel(float* __restrict__ X, const int* __restrict__ pos,
                            int nrows) {
    int idx = blockIdx.x * blockDim.x + threadIdx.x;
    int total = nrows << 10;
    if (idx >= total) return;
    int j = idx & 63;
    int h = (idx >> 6) & 15;
    int row = idx >> 10;
    float p = (float)pos[row];
    float th = p * g_invfreq[j];
    float sn, cs;
    sincosf(th, &sn, &cs);
    size_t base = (size_t)row * DM + h * DHD + j;
    float x1 = X[base], x2 = X[base + 64];
    X[base] = x1 * cs - x2 * sn;
    X[base + 64] = x2 * cs + x1 * sn;
}

// ---------------- flash attention, 64q x 64k tiles, DH=128 ----------------
// Causal mask analytic (mask0 is tril): keep iff k_col <= src_row.
// smem: Qs[128][64] | Ks[128][64] (St[64][64] overlays Ks) | Vs[64][128]
#define ATT_SMEM (24576 * 4)

__global__ void __launch_bounds__(256, 2) attn_kernel(
    const float* __restrict__ Qf, const float* __restrict__ Kf,
    const float* __restrict__ Vf,
    const int* __restrict__ orderp, const int* __restrict__ nbp,
    float* __restrict__ CTX) {
    extern __shared__ float sm[];
    float(*Qs)[64] = (float(*)[64])(sm);
    float(*Ks)[64] = (float(*)[64])(sm + 8192);
    float(*St)[64] = (float(*)[64])(sm + 8192);  // overlays Ks (sync-guarded)
    float(*Vs)[128] = (float(*)[128])(sm + 16384);
    __shared__ int s_src[64];

    int qt = blockIdx.x, h = blockIdx.y, b = blockIdx.z;
    int tid = threadIdx.x;
    int tx = tid & 15, ty = tid >> 4;
    int q0 = qt * 64;
    int nb = nbp[b];
    if (nb > MAXL) nb = MAXL;
    int nvalid = nb - q0;
    if (nvalid > 64) nvalid = 64;

    size_t ctx_base = ((size_t)b * MAXL + q0) * DM + (size_t)h * DHD;

    if (nvalid <= 0) {
        float4 z = make_float4(0.f, 0.f, 0.f, 0.f);
        for (int i = tid; i < 64 * 32; i += 256) {
            int m = i >> 5, c4 = (i & 31) << 2;
            *(float4*)&CTX[ctx_base + (size_t)m * DM + c4] = z;
        }
        return;
    }

    if (tid < 64) s_src[tid] = orderp[b * MAXL + q0 + tid];

    for (int i = tid; i < 64 * 32; i += 256) {
        int m = i >> 5, d4 = (i & 31) << 2;
        float4 v = *(const float4*)&Qf[((size_t)b * MAXL + q0 + m) * DM + h * DHD + d4];
        Qs[d4][m] = v.x; Qs[d4 + 1][m] = v.y;
        Qs[d4 + 2][m] = v.z; Qs[d4 + 3][m] = v.w;
    }
    __syncthreads();

    int smax = s_src[nvalid - 1];
    int nkt = (smax >> 6) + 1;

    int srow[4];
#pragma unroll
    for (int r = 0; r < 4; r++) {
        int qr = ty * 4 + r;
        srow[r] = (qr < nvalid) ? s_src[qr] : -1;
    }

    float m_r[4], l_r[4], acc[4][8];
#pragma unroll
    for (int r = 0; r < 4; r++) {
        m_r[r] = -1e30f; l_r[r] = 0.f;
#pragma unroll
        for (int c = 0; c < 8; c++) acc[r][c] = 0.f;
    }

    for (int kt = 0; kt < nkt; kt++) {
        int kbase = kt * 64;
        for (int i = tid; i < 64 * 32; i += 256) {
            int n = i >> 5, d4 = (i & 31) << 2;
            size_t goff = ((size_t)b * SS + kbase + n) * DM + h * DHD + d4;
            float4 kv = *(const float4*)&Kf[goff];
            Ks[d4][n] = kv.x; Ks[d4 + 1][n] = kv.y;
            Ks[d4 + 2][n] = kv.z; Ks[d4 + 3][n] = kv.w;
            *(float4*)&Vs[n][d4] = *(const float4*)&Vf[goff];
        }
        __syncthreads();

        float sc[4][4];
#pragma unroll
        for (int r = 0; r < 4; r++)
#pragma unroll
            for (int c = 0; c < 4; c++) sc[r][c] = 0.f;

#pragma unroll 16
        for (int d = 0; d < 128; d++) {
            float4 q4 = *(float4*)&Qs[d][ty * 4];
            float4 k4 = *(float4*)&Ks[d][tx * 4];
            float qa[4] = {q4.x, q4.y, q4.z, q4.w};
            float ka[4] = {k4.x, k4.y, k4.z, k4.w};
#pragma unroll
            for (int r = 0; r < 4; r++)
#pragma unroll
                for (int c = 0; c < 4; c++)
                    sc[r][c] = fmaf(qa[r], ka[c], sc[r][c]);
        }
        __syncthreads();  // done reading Ks before St (overlay) writes

#pragma unroll
        for (int r = 0; r < 4; r++) {
            float pv[4];
            float mx = -1e30f;
#pragma unroll
            for (int c = 0; c < 4; c++) {
                int kcol = kbase + tx * 4 + c;
                int keep = (kcol <= srow[r]);
                float v = keep ? sc[r][c] * SM_SCALE : -1e30f;
                pv[c] = v;
                mx = fmaxf(mx, v);
            }
#pragma unroll
            for (int off = 8; off > 0; off >>= 1)
                mx = fmaxf(mx, __shfl_xor_sync(0xffffffffu, mx, off));
            float mnew = fmaxf(m_r[r], mx);
            float corr = __expf(m_r[r] - mnew);
            float rs = 0.f;
#pragma unroll
            for (int c = 0; c < 4; c++) {
                float e = __expf(pv[c] - mnew);
                pv[c] = e;
                rs += e;
            }
#pragma unroll
            for (int off = 8; off > 0; off >>= 1)
                rs += __shfl_xor_sync(0xffffffffu, rs, off);
            l_r[r] = l_r[r] * corr + rs;
            m_r[r] = mnew;
#pragma unroll
            for (int c = 0; c < 8; c++) acc[r][c] *= corr;
#pragma unroll
            for (int c = 0; c < 4; c++) St[tx * 4 + c][ty * 4 + r] = pv[c];
        }
        __syncthreads();

#pragma unroll 8
        for (int n = 0; n < 64; n++) {
            float4 p4 = *(float4*)&St[n][ty * 4];
            float4 v0 = *(float4*)&Vs[n][tx * 8];
            float4 v1 = *(float4*)&Vs[n][tx * 8 + 4];
            float pa[4] = {p4.x, p4.y, p4.z, p4.w};
            float va[8] = {v0.x, v0.y, v0.z, v0.w, v1.x, v1.y, v1.z, v1.w};
#pragma unroll
            for (int r = 0; r < 4; r++)
#pragma unroll
                for (int c = 0; c < 8; c++)
                    acc[r][c] = fmaf(pa[r], va[c], acc[r][c]);
        }
        __syncthreads();
    }

#pragma unroll
    for (int r = 0; r < 4; r++) {
        int mrow = ty * 4 + r;
        float inv = (mrow < nvalid && l_r[r] > 0.f) ? (1.f / l_r[r]) : 0.f;
        float4 o0 = make_float4(acc[r][0] * inv, acc[r][1] * inv,
                                acc[r][2] * inv, acc[r][3] * inv);
        float4 o1 = make_float4(acc[r][4] * inv, acc[r][5] * inv,
                                acc[r][6] * inv, acc[r][7] * inv);
        *(float4*)&CTX[ctx_base + (size_t)mrow * DM + tx * 8] = o0;
        *(float4*)&CTX[ctx_base + (size_t)mrow * DM + tx * 8 + 4] = o1;
    }
}

// ---------------- launch ----------------------------------------------------
extern "C" void kernel_launch(void* const* d_in, const int* in_sizes, int n_in,
                              void* d_out, int out_size) {
    const float* q_src = (const float*)d_in[0];
    const float* k_src = (const float*)d_in[1];
    const float* v_src = (const float*)d_in[2];
    const float* Wq = (const float*)d_in[3];
    const float* Wk = (const float*)d_in[4];
    const float* Wv = (const float*)d_in[5];
    const float* Wo = (const float*)d_in[6];
    // d_in[7] = mask0 (causal tril, computed analytically)
    const int* pos_full = (const int*)d_in[8];
    const void* skip = (const void*)d_in[9];
    float* out = (float*)d_out;

    float *pQ, *pK, *pV, *pC;
    int *pPosq, *pOrd, *pNb;
    cudaGetSymbolAddress((void**)&pQ, g_Q);
    cudaGetSymbolAddress((void**)&pK, g_K);
    cudaGetSymbolAddress((void**)&pV, g_V);
    cudaGetSymbolAddress((void**)&pC, g_CTX);
    cudaGetSymbolAddress((void**)&pPosq, g_posq);
    cudaGetSymbolAddress((void**)&pOrd, g_order);
    cudaGetSymbolAddress((void**)&pNb, g_nb);

    cudaFuncSetAttribute(attn_kernel, cudaFuncAttributeMaxDynamicSharedMemorySize,
                         ATT_SMEM);

    init_invfreq_kernel<<<1, 64>>>();
    detect_bool_kernel<<<1, 256>>>((const unsigned int*)skip);
    trim_kernel<<<BB, 1024>>>(skip, pos_full);

    // projections (double-buffered SGEMM)
    sgemm_db<<<dim3(16, 32), 256>>>(q_src, Wq, pQ, BB * MAXL, DM, DM);
    sgemm_db<<<dim3(16, 64), 256>>>(k_src, Wk, pK, BB * SS, DM, DM);
    sgemm_db<<<dim3(16, 64), 256>>>(v_src, Wv, pV, BB * SS, DM, DM);

    // RoPE
    {
        int tq = (BB * MAXL) << 10;
        rope_kernel<<<(tq + 255) / 256, 256>>>(pQ, pPosq, BB * MAXL);
        int tk = (BB * SS) << 10;
        rope_kernel<<<(tk + 255) / 256, 256>>>(pK, pos_full, BB * SS);
    }

    // attention
    attn_kernel<<<dim3(16, HH, BB), 256, ATT_SMEM>>>(pQ, pK, pV, pOrd, pNb, pC);

    // output projection straight into d_out
    sgemm_db<<<dim3(16, 32), 256>>>(pC, Wo, out, BB * MAXL, DM, DM);
}

// round 6
// speedup vs baseline: 1.2430x; 1.2430x over previous
#include <cuda_runtime.h>
#include <math.h>
#include <stdint.h>

#define BB 4
#define SS 2048
#define DM 2048
#define HH 16
#define DHD 128
#define MAXL 1024
#define SM_SCALE 0.08838834764831845f  // 1/sqrt(128)

// ---------------- scratch (device globals; no allocation allowed) ----------
__device__ float g_Q[(size_t)BB * MAXL * DM];   // 33.5 MB
__device__ float g_K[(size_t)BB * SS * DM];     // 67 MB
__device__ float g_V[(size_t)BB * SS * DM];     // 67 MB
__device__ float g_CTX[(size_t)BB * MAXL * DM]; // 33.5 MB
__device__ int   g_order[BB * MAXL];
__device__ int   g_posq[BB * MAXL];
__device__ int   g_nb[BB];
__device__ float g_invfreq[64];
__device__ int   g_bool_kind;  // 0 = uint8, 1 = int32, 2 = float32

// ---------------- inv_freq init (match jax 10000**(j/64) in double) --------
__global__ void init_invfreq_kernel() {
    int j = threadIdx.x;
    if (j < 64) g_invfreq[j] = (float)(1.0 / pow(10000.0, (double)j / 64.0));
}

// ---------------- detect storage dtype of the bool skip_mask ---------------
__global__ void detect_bool_kernel(const unsigned int* __restrict__ w) {
    __shared__ int c01, c0f;
    if (threadIdx.x == 0) { c01 = 0; c0f = 0; }
    __syncthreads();
    int a = 0, f = 0;
    for (int i = threadIdx.x; i < 2048; i += blockDim.x) {
        unsigned int v = w[i];
        if (v == 0u || v == 1u) a++;
        if (v == 0u || v == 0x3F800000u) f++;
    }
    atomicAdd(&c01, a);
    atomicAdd(&c0f, f);
    __syncthreads();
    if (threadIdx.x == 0)
        g_bool_kind = (c01 == 2048) ? 1 : ((c0f == 2048) ? 2 : 0);
}

__device__ __forceinline__ int read_bool(const void* p, size_t i, int kind) {
    if (kind == 1) return ((const int*)p)[i] != 0;
    if (kind == 2) return ((const float*)p)[i] != 0.0f;
    return ((const unsigned char*)p)[i] != 0;
}

// ---------------- trim: stable True-first order + lengths + pos_trim -------
__global__ void trim_kernel(const void* __restrict__ skip,
                            const int* __restrict__ pos_full) {
    int b = blockIdx.x;
    int t = threadIdx.x;  // 1024 threads
    int kind = g_bool_kind;
    __shared__ int bufA[2048], bufB[2048];
    int m0 = read_bool(skip, (size_t)b * SS + t, kind);
    int m1 = read_bool(skip, (size_t)b * SS + t + 1024, kind);
    bufA[t] = m0;
    bufA[t + 1024] = m1;
    __syncthreads();
    int* srcb = bufA;
    int* dstb = bufB;
    for (int off = 1; off < 2048; off <<= 1) {
        int i0 = t, i1 = t + 1024;
        int v0 = srcb[i0] + (i0 >= off ? srcb[i0 - off] : 0);
        int v1 = srcb[i1] + (i1 >= off ? srcb[i1 - off] : 0);
        dstb[i0] = v0;
        dstb[i1] = v1;
        __syncthreads();
        int* tp = srcb; srcb = dstb; dstb = tp;
    }
    int total = srcb[2047];
    {
        int inc0 = srcb[t];
        int r0 = m0 ? (inc0 - 1) : (total + (t - inc0));
        if (r0 < MAXL) g_order[b * MAXL + r0] = t;
        int idx = t + 1024;
        int inc1 = srcb[idx];
        int r1 = m1 ? (inc1 - 1) : (total + (idx - inc1));
        if (r1 < MAXL) g_order[b * MAXL + r1] = idx;
    }
    __syncthreads();
    if (t < MAXL) {
        int s = g_order[b * MAXL + t];
        g_posq[b * MAXL + t] = (t < total) ? pos_full[b * SS + s] : 0;
    }
    if (t == 0) g_nb[b] = total;
}

// ---------------- SGEMM 128x128x16, double-buffered, conflict-free ---------
// Thread owns rows ty*8..+7 and cols {tx*4..+3, 64+tx*4..+3} (16B-stride
// LDS reads -> 256B contiguous per warp -> zero bank conflicts).
// Optional ragged row-skip: nbp != 0 -> blocks fully past nbp[batch] skip
// (zero_skip: write zeros first).
__global__ void __launch_bounds__(256, 2) sgemm_db(const float* __restrict__ A,
                                                   const float* __restrict__ Bm,
                                                   float* __restrict__ C,
                                                   int M, int N, int K,
                                                   const int* nbp, int rows_pb,
                                                   int zero_skip) {
    __shared__ float As[2][16][128];
    __shared__ float Bs[2][16][128];
    int tid = threadIdx.x;
    int tx = tid & 15, ty = tid >> 4;
    int row0 = blockIdx.y * 128, col0 = blockIdx.x * 128;

    if (nbp) {
        int b = row0 / rows_pb;
        int local = row0 - b * rows_pb;
        if (local >= nbp[b]) {
            if (zero_skip) {
                float4 z = make_float4(0.f, 0.f, 0.f, 0.f);
                for (int i = tid; i < 128 * 32; i += 256) {
                    int r = i >> 5, c4 = (i & 31) << 2;
                    *(float4*)&C[(size_t)(row0 + r) * N + col0 + c4] = z;
                }
            }
            return;
        }
    }

    int ar = tid >> 2, ac = (tid & 3) << 2;
    int br = tid >> 5, bc = (tid & 31) << 2;

    const float* Ap0 = A + (size_t)(row0 + ar) * K + ac;
    const float* Ap1 = A + (size_t)(row0 + ar + 64) * K + ac;
    const float* Bp0 = Bm + (size_t)br * N + col0 + bc;
    const float* Bp1 = Bm + (size_t)(br + 8) * N + col0 + bc;

    float acc[8][8];
#pragma unroll
    for (int i = 0; i < 8; i++)
#pragma unroll
        for (int j = 0; j < 8; j++) acc[i][j] = 0.f;

    const int NC = K >> 4;

    float4 pa0 = *(const float4*)Ap0;
    float4 pa1 = *(const float4*)Ap1;
    float4 pb0 = *(const float4*)Bp0;
    float4 pb1 = *(const float4*)Bp1;
    As[0][ac + 0][ar] = pa0.x; As[0][ac + 1][ar] = pa0.y;
    As[0][ac + 2][ar] = pa0.z; As[0][ac + 3][ar] = pa0.w;
    As[0][ac + 0][ar + 64] = pa1.x; As[0][ac + 1][ar + 64] = pa1.y;
    As[0][ac + 2][ar + 64] = pa1.z; As[0][ac + 3][ar + 64] = pa1.w;
    *(float4*)&Bs[0][br][bc] = pb0;
    *(float4*)&Bs[0][br + 8][bc] = pb1;
    pa0 = *(const float4*)(Ap0 + 16);
    pa1 = *(const float4*)(Ap1 + 16);
    pb0 = *(const float4*)(Bp0 + (size_t)16 * N);
    pb1 = *(const float4*)(Bp1 + (size_t)16 * N);
    __syncthreads();

    for (int c = 0; c < NC; ++c) {
        int buf = c & 1;
#pragma unroll
        for (int kk = 0; kk < 16; kk++) {
            float a[8], bb[8];
            *(float4*)&a[0] = *(float4*)&As[buf][kk][ty * 8];
            *(float4*)&a[4] = *(float4*)&As[buf][kk][ty * 8 + 4];
            *(float4*)&bb[0] = *(float4*)&Bs[buf][kk][tx * 4];        // 16B stride
            *(float4*)&bb[4] = *(float4*)&Bs[buf][kk][64 + tx * 4];   // 16B stride
#pragma unroll
            for (int i = 0; i < 8; i++)
#pragma unroll
                for (int j = 0; j < 8; j++)
                    acc[i][j] = fmaf(a[i], bb[j], acc[i][j]);
        }
        if (c + 1 < NC) {
            int nb = buf ^ 1;
            As[nb][ac + 0][ar] = pa0.x; As[nb][ac + 1][ar] = pa0.y;
            As[nb][ac + 2][ar] = pa0.z; As[nb][ac + 3][ar] = pa0.w;
            As[nb][ac + 0][ar + 64] = pa1.x; As[nb][ac + 1][ar + 64] = pa1.y;
            As[nb][ac + 2][ar + 64] = pa1.z; As[nb][ac + 3][ar + 64] = pa1.w;
            *(float4*)&Bs[nb][br][bc] = pb0;
            *(float4*)&Bs[nb][br + 8][bc] = pb1;
            if (c + 2 < NC) {
                int ko = (c + 2) << 4;
                pa0 = *(const float4*)(Ap0 + ko);
                pa1 = *(const float4*)(Ap1 + ko);
                pb0 = *(const float4*)(Bp0 + (size_t)ko * N);
                pb1 = *(const float4*)(Bp1 + (size_t)ko * N);
            }
        }
        __syncthreads();
    }

#pragma unroll
    for (int i = 0; i < 8; i++) {
        float* rowp = &C[(size_t)(row0 + ty * 8 + i) * N + col0];
        *(float4*)(rowp + tx * 4) =
            make_float4(acc[i][0], acc[i][1], acc[i][2], acc[i][3]);
        *(float4*)(rowp + 64 + tx * 4) =
            make_float4(acc[i][4], acc[i][5], acc[i][6], acc[i][7]);
    }
}

// ---------------- RoPE (in place on flat [rows, 2048]) ---------------------
__global__ void rope_kernel(float* __restrict__ X, const int* __restrict__ pos,
                            int nrows) {
    int idx = blockIdx.x * blockDim.x + threadIdx.x;
    int total = nrows << 10;
    if (idx >= total) return;
    int j = idx & 63;
    int h = (idx >> 6) & 15;
    int row = idx >> 10;
    float p = (float)pos[row];
    float th = p * g_invfreq[j];
    float sn, cs;
    sincosf(th, &sn, &cs);
    size_t base = (size_t)row * DM + h * DHD + j;
    float x1 = X[base], x2 = X[base + 64];
    X[base] = x1 * cs - x2 * sn;
    X[base + 64] = x2 * cs + x1 * sn;
}

// ---------------- flash attention, 64q x 64k tiles, DH=128 ----------------
// Causal mask analytic (mask0 is tril): keep iff k_col <= src_row.
// smem: Qs[128][64] | Ks[128][64] (St[64][64] overlays Ks) | Vs[64][128]
// V columns split {tx*4, 64+tx*4} for conflict-free LDS.
#define ATT_SMEM (24576 * 4)

__global__ void __launch_bounds__(256, 2) attn_kernel(
    const float* __restrict__ Qf, const float* __restrict__ Kf,
    const float* __restrict__ Vf,
    const int* __restrict__ orderp, const int* __restrict__ nbp,
    float* __restrict__ CTX) {
    extern __shared__ float sm[];
    float(*Qs)[64] = (float(*)[64])(sm);
    float(*Ks)[64] = (float(*)[64])(sm + 8192);
    float(*St)[64] = (float(*)[64])(sm + 8192);  // overlays Ks (sync-guarded)
    float(*Vs)[128] = (float(*)[128])(sm + 16384);
    __shared__ int s_src[64];

    int qt = blockIdx.x, h = blockIdx.y, b = blockIdx.z;
    int tid = threadIdx.x;
    int tx = tid & 15, ty = tid >> 4;
    int q0 = qt * 64;
    int nb = nbp[b];
    if (nb > MAXL) nb = MAXL;
    int nvalid = nb - q0;
    if (nvalid > 64) nvalid = 64;

    size_t ctx_base = ((size_t)b * MAXL + q0) * DM + (size_t)h * DHD;

    if (nvalid <= 0) {
        float4 z = make_float4(0.f, 0.f, 0.f, 0.f);
        for (int i = tid; i < 64 * 32; i += 256) {
            int m = i >> 5, c4 = (i & 31) << 2;
            *(float4*)&CTX[ctx_base + (size_t)m * DM + c4] = z;
        }
        return;
    }

    if (tid < 64) s_src[tid] = orderp[b * MAXL + q0 + tid];

    for (int i = tid; i < 64 * 32; i += 256) {
        int m = i >> 5, d4 = (i & 31) << 2;
        float4 v = *(const float4*)&Qf[((size_t)b * MAXL + q0 + m) * DM + h * DHD + d4];
        Qs[d4][m] = v.x; Qs[d4 + 1][m] = v.y;
        Qs[d4 + 2][m] = v.z; Qs[d4 + 3][m] = v.w;
    }
    __syncthreads();

    int smax = s_src[nvalid - 1];
    int nkt = (smax >> 6) + 1;

    int srow[4];
#pragma unroll
    for (int r = 0; r < 4; r++) {
        int qr = ty * 4 + r;
        srow[r] = (qr < nvalid) ? s_src[qr] : -1;
    }

    float m_r[4], l_r[4], acc[4][8];
#pragma unroll
    for (int r = 0; r < 4; r++) {
        m_r[r] = -1e30f; l_r[r] = 0.f;
#pragma unroll
        for (int c = 0; c < 8; c++) acc[r][c] = 0.f;
    }

    for (int kt = 0; kt < nkt; kt++) {
        int kbase = kt * 64;
        for (int i = tid; i < 64 * 32; i += 256) {
            int n = i >> 5, d4 = (i & 31) << 2;
            size_t goff = ((size_t)b * SS + kbase + n) * DM + h * DHD + d4;
            float4 kv = *(const float4*)&Kf[goff];
            Ks[d4][n] = kv.x; Ks[d4 + 1][n] = kv.y;
            Ks[d4 + 2][n] = kv.z; Ks[d4 + 3][n] = kv.w;
            *(float4*)&Vs[n][d4] = *(const float4*)&Vf[goff];
        }
        __syncthreads();

        float sc[4][4];
#pragma unroll
        for (int r = 0; r < 4; r++)
#pragma unroll
            for (int c = 0; c < 4; c++) sc[r][c] = 0.f;

#pragma unroll 16
        for (int d = 0; d < 128; d++) {
            float4 q4 = *(float4*)&Qs[d][ty * 4];
            float4 k4 = *(float4*)&Ks[d][tx * 4];
            float qa[4] = {q4.x, q4.y, q4.z, q4.w};
            float ka[4] = {k4.x, k4.y, k4.z, k4.w};
#pragma unroll
            for (int r = 0; r < 4; r++)
#pragma unroll
                for (int c = 0; c < 4; c++)
                    sc[r][c] = fmaf(qa[r], ka[c], sc[r][c]);
        }
        __syncthreads();  // done reading Ks before St (overlay) writes

#pragma unroll
        for (int r = 0; r < 4; r++) {
            float pv[4];
            float mx = -1e30f;
#pragma unroll
            for (int c = 0; c < 4; c++) {
                int kcol = kbase + tx * 4 + c;
                int keep = (kcol <= srow[r]);
                float v = keep ? sc[r][c] * SM_SCALE : -1e30f;
                pv[c] = v;
                mx = fmaxf(mx, v);
            }
#pragma unroll
            for (int off = 8; off > 0; off >>= 1)
                mx = fmaxf(mx, __shfl_xor_sync(0xffffffffu, mx, off));
            float mnew = fmaxf(m_r[r], mx);
            float corr = __expf(m_r[r] - mnew);
            float rs = 0.f;
#pragma unroll
            for (int c = 0; c < 4; c++) {
                float e = __expf(pv[c] - mnew);
                pv[c] = e;
                rs += e;
            }
#pragma unroll
            for (int off = 8; off > 0; off >>= 1)
                rs += __shfl_xor_sync(0xffffffffu, rs, off);
            l_r[r] = l_r[r] * corr + rs;
            m_r[r] = mnew;
#pragma unroll
            for (int c = 0; c < 8; c++) acc[r][c] *= corr;
#pragma unroll
            for (int c = 0; c < 4; c++) St[tx * 4 + c][ty * 4 + r] = pv[c];
        }
        __syncthreads();

#pragma unroll 8
        for (int n = 0; n < 64; n++) {
            float4 p4 = *(float4*)&St[n][ty * 4];
            float4 v0 = *(float4*)&Vs[n][tx * 4];        // 16B stride
            float4 v1 = *(float4*)&Vs[n][64 + tx * 4];   // 16B stride
            float pa[4] = {p4.x, p4.y, p4.z, p4.w};
            float va[8] = {v0.x, v0.y, v0.z, v0.w, v1.x, v1.y, v1.z, v1.w};
#pragma unroll
            for (int r = 0; r < 4; r++)
#pragma unroll
                for (int c = 0; c < 8; c++)
                    acc[r][c] = fmaf(pa[r], va[c], acc[r][c]);
        }
        __syncthreads();
    }

#pragma unroll
    for (int r = 0; r < 4; r++) {
        int mrow = ty * 4 + r;
        float inv = (mrow < nvalid && l_r[r] > 0.f) ? (1.f / l_r[r]) : 0.f;
        float4 o0 = make_float4(acc[r][0] * inv, acc[r][1] * inv,
                                acc[r][2] * inv, acc[r][3] * inv);
        float4 o1 = make_float4(acc[r][4] * inv, acc[r][5] * inv,
                                acc[r][6] * inv, acc[r][7] * inv);
        *(float4*)&CTX[ctx_base + (size_t)mrow * DM + tx * 4] = o0;
        *(float4*)&CTX[ctx_base + (size_t)mrow * DM + 64 + tx * 4] = o1;
    }
}

// ---------------- launch ----------------------------------------------------
extern "C" void kernel_launch(void* const* d_in, const int* in_sizes, int n_in,
                              void* d_out, int out_size) {
    const float* q_src = (const float*)d_in[0];
    const float* k_src = (const float*)d_in[1];
    const float* v_src = (const float*)d_in[2];
    const float* Wq = (const float*)d_in[3];
    const float* Wk = (const float*)d_in[4];
    const float* Wv = (const float*)d_in[5];
    const float* Wo = (const float*)d_in[6];
    // d_in[7] = mask0 (causal tril, computed analytically)
    const int* pos_full = (const int*)d_in[8];
    const void* skip = (const void*)d_in[9];
    float* out = (float*)d_out;

    float *pQ, *pK, *pV, *pC;
    int *pPosq, *pOrd, *pNb;
    cudaGetSymbolAddress((void**)&pQ, g_Q);
    cudaGetSymbolAddress((void**)&pK, g_K);
    cudaGetSymbolAddress((void**)&pV, g_V);
    cudaGetSymbolAddress((void**)&pC, g_CTX);
    cudaGetSymbolAddress((void**)&pPosq, g_posq);
    cudaGetSymbolAddress((void**)&pOrd, g_order);
    cudaGetSymbolAddress((void**)&pNb, g_nb);

    cudaFuncSetAttribute(attn_kernel, cudaFuncAttributeMaxDynamicSharedMemorySize,
                         ATT_SMEM);

    init_invfreq_kernel<<<1, 64>>>();
    detect_bool_kernel<<<1, 256>>>((const unsigned int*)skip);
    trim_kernel<<<BB, 1024>>>(skip, pos_full);

    // projections (conflict-free double-buffered SGEMM; Q skips padded rows)
    sgemm_db<<<dim3(16, 32), 256>>>(q_src, Wq, pQ, BB * MAXL, DM, DM, pNb, MAXL, 0);
    sgemm_db<<<dim3(16, 64), 256>>>(k_src, Wk, pK, BB * SS, DM, DM, (const int*)0, 0, 0);
    sgemm_db<<<dim3(16, 64), 256>>>(v_src, Wv, pV, BB * SS, DM, DM, (const int*)0, 0, 0);

    // RoPE
    {
        int tq = (BB * MAXL) << 10;
        rope_kernel<<<(tq + 255) / 256, 256>>>(pQ, pPosq, BB * MAXL);
        int tk = (BB * SS) << 10;
        rope_kernel<<<(tk + 255) / 256, 256>>>(pK, pos_full, BB * SS);
    }

    // attention
    attn_kernel<<<dim3(16, HH, BB), 256, ATT_SMEM>>>(pQ, pK, pV, pOrd, pNb, pC);

    // output projection straight into d_out (zero-fill skipped padded rows)
    sgemm_db<<<dim3(16, 32), 256>>>(pC, Wo, out, BB * MAXL, DM, DM, pNb, MAXL, 1);
}